// round 17
// baseline (speedup 1.0000x reference)
#include <cuda_runtime.h>
#include <stdint.h>

// HakesPQ forward: out[n, m*16:(m+1)*16] = codebooks[m, k*, :]
// k* = argmin_k fl( fl(v2 - 2*<v,c_k>) + |c_k|^2 ) with RN at each elementwise
// step, exact fp32 emulation of the reference (jax/XLA-CPU): all reductions are
// sequential fmaf chains over d ascending; ties -> lowest k. FROZEN (rel_err==0).
// N=32768, D=768, M=48, KSUB=16, DSUB=16.
//
// R15: codebook k-loop reads moved to the CONSTANT PORT (warp-uniform LDC/ULDC)
// -> removes 2048 broadcast wavefronts/CTA (~40% of L1 crossbar traffic).
// Shared keeps v-tile staging + c2 + sidx + scb copy for the lane-divergent
// output gather. Otherwise identical to R13 (R=4 rows/thread, idx output).

#define N_VECS   32768
#define D_DIM    768
#define M_SUB    48
#define KSUB     16
#define DSUB     16

#define MG       8                    // m per CTA (blockIdx.y selects group)
#define COLS     (MG * DSUB)          // 128 v-columns per CTA
#define NROWS    128                  // rows per CTA
#define NTHREADS 256                  // 8 warps; warp w owns m=w, lanes own 4 rows
#define ROW_PAD  132                  // conflict-free LDS.128 on v tile
#define K_STRIDE 20                   // scb codeword stride (out-gather bank spread)
#define M_STRIDE (KSUB * K_STRIDE)    // 320 floats per m
#define IDX_PAD  132                  // sidx row pad in bytes

#define SV_FLOATS   (NROWS * ROW_PAD)          // 16896
#define SCB_FLOATS  (MG * M_STRIDE)            // 2560
#define SC2_FLOATS  (MG * KSUB)                // 128
#define SIDX_BYTES  (MG * IDX_PAD)             // 1056
#define SMEM_BYTES  ((SV_FLOATS + SCB_FLOATS + SC2_FLOATS) * 4 + SIDX_BYTES)

// full codebook in constant memory (48*16*16*4 = 49152 B <= 64KB bank)
__constant__ float ccb[M_SUB * KSUB * DSUB];

__global__ void __launch_bounds__(NTHREADS, 2)
pq_kernel(const float* __restrict__ vecs,
          const float* __restrict__ cb,
          float* __restrict__ out)
{
    extern __shared__ float smem[];
    float*   sv   = smem;                          // [NROWS][ROW_PAD]
    float*   scb  = smem + SV_FLOATS;              // [MG][KSUB][K_STRIDE] (out-gather)
    float*   sc2  = scb + SCB_FLOATS;              // [MG][KSUB]
    uint8_t* sidx = (uint8_t*)(sc2 + SC2_FLOATS);  // [MG][IDX_PAD]

    const int tid = threadIdx.x;
    const int mg  = blockIdx.y;                    // 0..5
    const float* cbg = cb + mg * (MG * KSUB * DSUB);

    // ---- scb copy (for output gather only), k-stride 20 ----
    {
        const float4* s = (const float4*)cbg;      // 512 float4
        #pragma unroll
        for (int t = 0; t < 2; t++) {
            int i = tid + t * NTHREADS;
            int q = i & 3;
            int k = (i >> 2) & 15;
            int m = i >> 6;
            *(float4*)(scb + m * M_STRIDE + k * K_STRIDE + q * 4) = s[i];
        }
    }
    // ---- |c|^2: one (m,k) per thread, frozen sequential fma chain ----
    if (tid < SC2_FLOATS) {
        const float* c = cbg + tid * DSUB;
        float s = 0.0f;
        #pragma unroll
        for (int d = 0; d < DSUB; d++) s = fmaf(c[d], c[d], s);
        sc2[tid] = s;
    }

    // ---- stage 128 rows x 128 cols in (coalesced float4) ----
    const long long row0 = (long long)blockIdx.x * NROWS;
    const float* vbase = vecs + row0 * D_DIM + mg * COLS;
    #pragma unroll
    for (int j = 0; j < 16; j++) {
        int i  = tid + j * NTHREADS;
        int r  = i >> 5;
        int c4 = i & 31;
        *(float4*)(sv + r * ROW_PAD + c4 * 4) =
            *(const float4*)(vbase + (long long)r * D_DIM + c4 * 4);
    }
    __syncthreads();

    const int w = tid >> 5;            // warp-uniform local m
    const int l = tid & 31;            // rows l, l+32, l+64, l+96

    // ---- load 4 rows' v chunks + frozen v2 chains ----
    float v[4][16];
    float v2[4];
    #pragma unroll
    for (int g = 0; g < 4; g++) {
        const float* p = sv + (l + 32 * g) * ROW_PAD + w * DSUB;
        float4 a0 = *(const float4*)(p + 0);
        float4 a1 = *(const float4*)(p + 4);
        float4 a2 = *(const float4*)(p + 8);
        float4 a3 = *(const float4*)(p + 12);
        v[g][0]=a0.x;  v[g][1]=a0.y;  v[g][2]=a0.z;  v[g][3]=a0.w;
        v[g][4]=a1.x;  v[g][5]=a1.y;  v[g][6]=a1.z;  v[g][7]=a1.w;
        v[g][8]=a2.x;  v[g][9]=a2.y;  v[g][10]=a2.z; v[g][11]=a2.w;
        v[g][12]=a3.x; v[g][13]=a3.y; v[g][14]=a3.z; v[g][15]=a3.w;
        float s = 0.0f;
        #pragma unroll
        for (int d = 0; d < DSUB; d++) s = fmaf(v[g][d], v[g][d], s);
        v2[g] = s;
    }

    // compute-phase codebook: CONSTANT memory, warp-uniform address -> LDC/ULDC
    const float* cmc = ccb + (mg * MG + w) * (KSUB * DSUB);
    const float* c2m = sc2 + w * KSUB;

    float best[4] = { 3.402823466e38f, 3.402823466e38f,
                      3.402823466e38f, 3.402823466e38f };
    int   bk[4]   = { 0, 0, 0, 0 };

    #pragma unroll
    for (int k = 0; k < KSUB; ++k) {
        const float4* ck4 = (const float4*)(cmc + k * DSUB);
        float4 c0 = ck4[0];                        // LDC.128 (constant port,
        float4 c1 = ck4[1];                        //  zero L1 crossbar traffic)
        float4 c2 = ck4[2];
        float4 c3 = ck4[3];
        float cw[16] = { c0.x,c0.y,c0.z,c0.w, c1.x,c1.y,c1.z,c1.w,
                         c2.x,c2.y,c2.z,c2.w, c3.x,c3.y,c3.z,c3.w };
        float acc0 = 0.0f, acc1 = 0.0f, acc2a = 0.0f, acc3 = 0.0f;
        #pragma unroll
        for (int d = 0; d < DSUB; d++) {           // 4 independent frozen chains
            acc0  = fmaf(v[0][d], cw[d], acc0);
            acc1  = fmaf(v[1][d], cw[d], acc1);
            acc2a = fmaf(v[2][d], cw[d], acc2a);
            acc3  = fmaf(v[3][d], cw[d], acc3);
        }
        float c2k = c2m[k];                        // broadcast scalar LDS (1 wf)
        // frozen elementwise ops, RN each step; strict < -> first max wins
        float t0 = __fadd_rn(__fsub_rn(v2[0], __fmul_rn(2.0f, acc0 )), c2k);
        if (t0 < best[0]) { best[0] = t0; bk[0] = k; }
        float t1 = __fadd_rn(__fsub_rn(v2[1], __fmul_rn(2.0f, acc1 )), c2k);
        if (t1 < best[1]) { best[1] = t1; bk[1] = k; }
        float t2 = __fadd_rn(__fsub_rn(v2[2], __fmul_rn(2.0f, acc2a)), c2k);
        if (t2 < best[2]) { best[2] = t2; bk[2] = k; }
        float t3 = __fadd_rn(__fsub_rn(v2[3], __fmul_rn(2.0f, acc3 )), c2k);
        if (t3 < best[3]) { best[3] = t3; bk[3] = k; }
    }

    // ---- publish winner indices ----
    #pragma unroll
    for (int g = 0; g < 4; g++)
        sidx[w * IDX_PAD + (l + 32 * g)] = (uint8_t)bk[g];
    __syncthreads();

    // ---- coalesced output: gather winner from scb (lane-divergent k), STG ----
    float* obase = out + row0 * D_DIM + mg * COLS;
    #pragma unroll
    for (int j = 0; j < 16; j++) {
        int i  = tid + j * NTHREADS;
        int r  = i >> 5;                           // warp covers one row
        int c4 = i & 31;
        int m  = c4 >> 2;                          // 4 lanes per m
        int q  = c4 & 3;
        int k  = sidx[m * IDX_PAD + r];
        float4 gv = *(const float4*)(scb + m * M_STRIDE + k * K_STRIDE + q * 4);
        *(float4*)(obase + (long long)r * D_DIM + c4 * 4) = gv;   // 512B/warp contiguous
    }
}

extern "C" void kernel_launch(void* const* d_in, const int* in_sizes, int n_in,
                              void* d_out, int out_size)
{
    const float* vecs = (const float*)d_in[0];   // (N, 768) f32
    const float* cb   = (const float*)d_in[1];   // (48, 16, 16) f32
    float*       out  = (float*)d_out;           // (N, 768) f32

    // fill constant codebook (D2D async memcpy: graph-capturable, deterministic)
    cudaMemcpyToSymbolAsync(ccb, cb, M_SUB * KSUB * DSUB * sizeof(float), 0,
                            cudaMemcpyDeviceToDevice);

    cudaFuncSetAttribute(pq_kernel, cudaFuncAttributeMaxDynamicSharedMemorySize, SMEM_BYTES);
    dim3 grid(N_VECS / NROWS, M_SUB / MG);       // (256, 6)
    pq_kernel<<<grid, NTHREADS, SMEM_BYTES>>>(vecs, cb, out);
}